// round 14
// baseline (speedup 1.0000x reference)
#include <cuda_runtime.h>
#include <cuda_bf16.h>
#include <stdint.h>

#define BB 8
#define AA 26880
#define KK 2048
#define NCH 105          // 26880/256 chunks per batch
#define SCAP 4096        // staged-key capacity (Nv ~ 1344)
#define PCAP 512         // conflict-pair capacity per batch (expected ~10)
#define RB 32            // rank/tail blocks per batch in K2
#define TILE 128         // K3 tile size
#define K3B 136          // max tiles per batch: nt<=16 -> 16*17/2 = 136

// ---------------- device scratch ----------------
__device__ unsigned            g_cvcnt[BB * NCH];          // per-chunk valid count
__device__ unsigned long long  g_ckeys[BB * NCH * 256];    // chunk-local compacted keys
__device__ int                 g_nv[BB];
__device__ float4              g_boxes[BB][KK];
__device__ unsigned            g_paircnt[BB];              // 0 at entry, reset by K3 winner
__device__ unsigned            g_pairs[BB][PCAP];
__device__ unsigned            g_tiledone[BB];             // 0 at entry, reset by K3 winner

// ======== K1: warp-per-chunk compaction (8 anchors/lane, no barriers, no smem) ========
// key = (score_bits << 32) | (0xFFFFFFFF - idx): descending key order gives
// score desc, idx asc on ties (positive floats are bit-order-preserving).
__global__ void __launch_bounds__(256) k1_compact(const float* __restrict__ preds) {
    int b = blockIdx.y;
    int t = threadIdx.x, wid = t >> 5, lane = t & 31;

    int chunk = blockIdx.x * 8 + wid;            // one warp = one 256-anchor chunk
    if (chunk >= NCH) {
        cudaTriggerProgrammaticLaunchCompletion();
        return;
    }

    const float* sc = preds + (size_t)b * 5 * AA + (size_t)4 * AA;
    int a0 = chunk * 256 + lane * 8;             // 8 consecutive anchors per lane
    float4 sA = *(const float4*)(sc + a0);       // MLP=2: both loads independent
    float4 sB = *(const float4*)(sc + a0 + 4);

    unsigned m = (unsigned)(sA.x >= 0.1f)
               | ((unsigned)(sA.y >= 0.1f) << 1)
               | ((unsigned)(sA.z >= 0.1f) << 2)
               | ((unsigned)(sA.w >= 0.1f) << 3)
               | ((unsigned)(sB.x >= 0.1f) << 4)
               | ((unsigned)(sB.y >= 0.1f) << 5)
               | ((unsigned)(sB.z >= 0.1f) << 6)
               | ((unsigned)(sB.w >= 0.1f) << 7);
    int v = __popc(m);
    int inc = v;
    #pragma unroll
    for (int off = 1; off < 32; off <<= 1) {
        int n = __shfl_up_sync(0xFFFFFFFFu, inc, off);
        if (lane >= off) inc += n;
    }
    unsigned p = (unsigned)(inc - v);            // exclusive prefix within chunk

    unsigned long long* dst = &g_ckeys[((size_t)b * NCH + chunk) * 256];
    float ss[8] = {sA.x, sA.y, sA.z, sA.w, sB.x, sB.y, sB.z, sB.w};
    #pragma unroll
    for (int q = 0; q < 8; q++) {
        if ((m >> q) & 1u) {
            dst[p++] = ((unsigned long long)__float_as_uint(ss[q]) << 32) |
                       (unsigned long long)(0xFFFFFFFFu - (unsigned)(a0 + q));
        }
    }
    if (lane == 31) g_cvcnt[b * NCH + chunk] = (unsigned)inc;

    cudaTriggerProgrammaticLaunchCompletion();
}

// ======== K2: rank sort (thread-per-candidate, 4-way split scan) + tail fill ========
__global__ void __launch_bounds__(256) k2_rank_tail(const float* __restrict__ preds,
                                                    float* __restrict__ out) {
    cudaGridDependencySynchronize();             // K1's writes visible

    int b = blockIdx.y, bl = blockIdx.x;         // bl in [0, RB)
    int t = threadIdx.x, wid = t >> 5, lane = t & 31;

    __shared__ unsigned long long sk[SCAP];      // 32 KB
    __shared__ unsigned scv[NCH];
    __shared__ unsigned scpre[NCH + 1];
    __shared__ unsigned short rp[64][4];
    __shared__ unsigned wsum[8];
    __shared__ unsigned s_cnt;

    if (t < NCH) scv[t] = g_cvcnt[b * NCH + t];
    __syncthreads();
    if (t == 0) {
        unsigned run = 0;
        for (int x = 0; x < NCH; x++) { scpre[x] = run; run += scv[x]; }
        scpre[NCH] = run;
        s_cnt = (run > SCAP) ? SCAP : run;
    }
    __syncthreads();
    unsigned cnt = s_cnt;
    int Nv = ((int)cnt < KK) ? (int)cnt : KK;
    if (bl == 0 && t == 0) g_nv[b] = Nv;

    // stage keys contiguously (warp per chunk)
    for (int cl = wid; cl < NCH; cl += 8) {
        unsigned base = scpre[cl], n = scv[cl];
        const unsigned long long* src = &g_ckeys[((size_t)b * NCH + cl) * 256];
        for (unsigned j = lane; j < n; j += 32) {
            unsigned d = base + j;
            if (d < SCAP) sk[d] = __ldg(&src[j]);
        }
    }
    __syncthreads();

    // rank scan: slot = candidate lane, seg = key segment
    int slot = t & 63, seg = t >> 6;             // seg is warp-uniform
    int npass = ((int)cnt + RB * 64 - 1) / (RB * 64);
    const float* basep = preds + (size_t)b * 5 * AA;

    for (int p = 0; p < npass; p++) {
        int c = p * (RB * 64) + bl * 64 + slot;
        bool act = (c < (int)cnt);
        unsigned long long mykey = act ? sk[c] : 0ULL;
        int s0 = (int)(((long long)cnt * seg) >> 2);
        int s1 = (int)(((long long)cnt * (seg + 1)) >> 2);
        int rpart = 0;
        if (act) {
            int mm = s0;
            for (; mm + 4 <= s1; mm += 4) {      // broadcast LDS: all lanes same address
                rpart += (sk[mm]     > mykey);
                rpart += (sk[mm + 1] > mykey);
                rpart += (sk[mm + 2] > mykey);
                rpart += (sk[mm + 3] > mykey);
            }
            for (; mm < s1; mm++) rpart += (sk[mm] > mykey);
        }
        rp[slot][seg] = (unsigned short)rpart;
        __syncthreads();
        if (seg == 0 && act) {
            int r = (int)rp[slot][0] + rp[slot][1] + rp[slot][2] + rp[slot][3];
            if (r < KK) {
                int idx = (int)(0xFFFFFFFFu - (unsigned)(mykey & 0xFFFFFFFFu));
                float score = __uint_as_float((unsigned)(mykey >> 32));
                float cx = __ldg(&basep[idx]);
                float cy = __ldg(&basep[AA + idx]);
                float ww = __ldg(&basep[2 * AA + idx]);
                float hh = __ldg(&basep[3 * AA + idx]);
                float hw = ww * 0.5f, hv = hh * 0.5f;
                float x1 = cx - hw, y1 = cy - hv, x2 = cx + hw, y2 = cy + hv;
                g_boxes[b][r] = make_float4(x1, y1, x2, y2);
                // scale = DET_SCALE/IMG_SIZE = [1.5, 1.0546875] (exact fp32)
                float s1f = x1 * 1.5f + 1.0f;
                float s2f = y1 * 1.0546875f + 1.0f;
                float s3f = x2 * 1.5f + 1.0f;
                float s4f = y2 * 1.0546875f + 1.0f;
                float* d = out + ((size_t)b * KK + r) * 5;
                d[0] = (s1f + s3f) * 0.5f;
                d[1] = (s2f + s4f) * 0.5f;
                d[2] = s3f - s1f;
                d[3] = s4f - s2f;
                d[4] = score;
                out[(size_t)BB * KK * 5 + (size_t)b * KK + r] = 1.0f;
            }
        }
        __syncthreads();
    }

    // tail fill: this block handles chunks bl, bl+RB, ...
    int needed = KK - Nv;
    if (needed > 0) {
        const float* sc = basep + (size_t)4 * AA;
        for (int cl = bl; cl < NCH; cl += RB) {
            int invpre = 256 * cl - (int)scpre[cl];   // block-uniform
            if (invpre < needed) {                    // uniform branch
                int a = cl * 256 + t;
                float s = __ldg(&sc[a]);
                bool inv = (s < 0.1f);
                unsigned bal = __ballot_sync(0xFFFFFFFFu, inv);
                if (lane == 0) wsum[wid] = (unsigned)__popc(bal);
                __syncthreads();
                int wbase = 0;
                #pragma unroll
                for (int q = 0; q < 8; q++) if (q < wid) wbase += (int)wsum[q];
                int r = invpre + wbase + __popc(bal & ((1u << lane) - 1u));
                if (inv && r < needed) {
                    int slotk = Nv + r;
                    float cx = basep[a], cy = basep[AA + a];
                    float ww = basep[2 * AA + a], hh = basep[3 * AA + a];
                    float hw = ww * 0.5f, hv = hh * 0.5f;
                    float x1 = cx - hw, y1 = cy - hv, x2 = cx + hw, y2 = cy + hv;
                    float s1f = x1 * 1.5f + 1.0f;
                    float s2f = y1 * 1.0546875f + 1.0f;
                    float s3f = x2 * 1.5f + 1.0f;
                    float s4f = y2 * 1.0546875f + 1.0f;
                    float* d = out + ((size_t)b * KK + slotk) * 5;
                    d[0] = (s1f + s3f) * 0.5f;
                    d[1] = (s2f + s4f) * 0.5f;
                    d[2] = s3f - s1f;
                    d[3] = s4f - s2f;
                    d[4] = -1.0f;
                    out[(size_t)BB * KK * 5 + (size_t)b * KK + slotk] = 0.0f;
                }
                __syncthreads();   // wsum reuse guard (uniform)
            }
        }
    }

    cudaTriggerProgrammaticLaunchCompletion();
}

// ======== K3: conflict pairs (128x128 tiles) + last-tile-done greedy resolution ========
__global__ void __launch_bounds__(256) k3_pairs_resolve(float* __restrict__ out) {
    cudaGridDependencySynchronize();             // K2's writes visible

    int b = blockIdx.y, bx = blockIdx.x;
    int t = threadIdx.x;

    int Nv = __ldg(&g_nv[b]);
    int nt = (Nv + TILE - 1) / TILE;             // <= 16
    int T = nt * (nt + 1) / 2;                   // <= 136
    if (bx >= T) return;

    __shared__ float4 sbi[TILE];
    __shared__ float  sai[TILE];
    __shared__ float4 sbj[TILE];
    __shared__ float  saj[TILE];
    __shared__ int    swin;
    __shared__ unsigned sp[PCAP];        // 2 KB
    __shared__ unsigned char skeep[KK];  // 2 KB

    int i = 0, S = 0;
    while (bx >= S + (nt - i)) { S += nt - i; i++; }
    int j = i + (bx - S);
    int i0 = i * TILE, j0 = j * TILE;

    if (t < TILE) {
        float4 bi = (i0 + t < Nv) ? g_boxes[b][i0 + t] : make_float4(0.f, 0.f, 0.f, 0.f);
        sbi[t] = bi; sai[t] = (bi.z - bi.x) * (bi.w - bi.y);
    } else {
        int u = t - TILE;
        float4 bj = (j0 + u < Nv) ? g_boxes[b][j0 + u] : make_float4(0.f, 0.f, 0.f, 0.f);
        sbj[u] = bj; saj[u] = (bj.z - bj.x) * (bj.w - bj.y);
    }
    __syncthreads();

    int jl = t & (TILE - 1);                     // j column for this thread
    int jj = j0 + jl;
    if (jj < Nv) {
        float4 bj = sbj[jl];
        float aj = saj[jl];
        #pragma unroll 8
        for (int q = 0; q < TILE / 2; q++) {     // 64 i-rows per thread, stride 2
            int ii = (t >> 7) + q * 2;
            int gi = i0 + ii;
            if (gi >= Nv || gi >= jj) continue;
            float4 bi = sbi[ii];
            float lx = fmaxf(bi.x, bj.x), ly = fmaxf(bi.y, bj.y);
            float rx = fminf(bi.z, bj.z), ry = fminf(bi.w, bj.w);
            float iw = fmaxf(rx - lx, 0.f), ih = fmaxf(ry - ly, 0.f);
            float inter = iw * ih;
            // iou > 0.7  <=>  inter > 0.7 * union   (union > 0)
            if (inter > 0.7f * (sai[ii] + aj - inter)) {
                unsigned pos = atomicAdd(&g_paircnt[b], 1u);
                if (pos < PCAP)
                    g_pairs[b][pos] = ((unsigned)jj << 16) | (unsigned)gi;
            }
        }
    }
    __syncthreads();

    if (t == 0) {
        __threadfence();                                  // publish this tile's pair writes
        unsigned old = atomicAdd(&g_tiledone[b], 1u);
        swin = (old == (unsigned)(T - 1)) ? 1 : 0;
    }
    __syncthreads();
    if (!swin) return;

    // ---- winner block: exact greedy resolution ----
    __threadfence();
    unsigned n = g_paircnt[b];
    if (n > PCAP) n = PCAP;

    for (int k = t; k < KK; k += 256) skeep[k] = (k < Nv) ? 1 : 0;
    for (unsigned p = t; p < n; p += 256) sp[p] = g_pairs[b][p];
    __syncthreads();

    if (t == 0) {
        // sort ascending by packed (j<<16 | i): process suppression targets j ascending
        for (unsigned x = 1; x < n; x++) {
            unsigned v = sp[x];
            int y = (int)x - 1;
            while (y >= 0 && sp[y] > v) { sp[y + 1] = sp[y]; y--; }
            sp[y + 1] = v;
        }
        for (unsigned x = 0; x < n; x++) {
            unsigned v = sp[x];
            int jd = (int)(v >> 16), is = (int)(v & 0xFFFFu);
            if (skeep[is] && skeep[jd]) {
                skeep[jd] = 0;
                out[(size_t)BB * KK * 5 + (size_t)b * KK + jd] = 0.0f;
            }
        }
        g_paircnt[b]  = 0u;   // restore zero-state for next launch
        g_tiledone[b] = 0u;
    }
}

// ---------------- launch (serial PDL pipeline, round-8 structure) ----------------
static void launch_pdl2(void (*kern)(const float*, float*),
                        dim3 grid, const float* preds, float* out) {
    cudaLaunchConfig_t cfg = {};
    cfg.gridDim = grid; cfg.blockDim = dim3(256, 1, 1);
    cfg.dynamicSmemBytes = 0; cfg.stream = 0;
    cudaLaunchAttribute attr[1];
    attr[0].id = cudaLaunchAttributeProgrammaticStreamSerialization;
    attr[0].val.programmaticStreamSerializationAllowed = 1;
    cfg.attrs = attr; cfg.numAttrs = 1;
    cudaLaunchKernelEx(&cfg, kern, preds, out);
}
static void launch_pdl1(void (*kern)(float*), dim3 grid, float* out) {
    cudaLaunchConfig_t cfg = {};
    cfg.gridDim = grid; cfg.blockDim = dim3(256, 1, 1);
    cfg.dynamicSmemBytes = 0; cfg.stream = 0;
    cudaLaunchAttribute attr[1];
    attr[0].id = cudaLaunchAttributeProgrammaticStreamSerialization;
    attr[0].val.programmaticStreamSerializationAllowed = 1;
    cfg.attrs = attr; cfg.numAttrs = 1;
    cudaLaunchKernelEx(&cfg, kern, out);
}

extern "C" void kernel_launch(void* const* d_in, const int* in_sizes, int n_in,
                              void* d_out, int out_size) {
    const float* preds = (const float*)d_in[0];
    float* out = (float*)d_out;
    (void)in_sizes; (void)n_in; (void)out_size;

    k1_compact<<<dim3(14, BB), 256>>>(preds);             // 14*8 warps >= 105 chunks
    launch_pdl2(k2_rank_tail, dim3(RB, BB), preds, out);  // PDL on K1
    launch_pdl1(k3_pairs_resolve, dim3(K3B, BB), out);    // PDL on K2
}

// round 16
// speedup vs baseline: 1.1204x; 1.1204x over previous
#include <cuda_runtime.h>
#include <cuda_bf16.h>
#include <stdint.h>

#define BB 8
#define AA 26880
#define KK 2048
#define NCH 105          // 26880/256 chunks per batch
#define SCAP 4096        // staged-key capacity (Nv ~ 1344)
#define PCAP 512         // conflict-pair capacity per batch (expected ~10)
#define RB 32            // rank/tail blocks per batch in K2
#define TILE 64          // K3 tile size (round-8 proven)
#define K3B 528          // max tiles per batch (Nv<=2048 -> nt<=32 -> 528)

// ---------------- device scratch ----------------
__device__ unsigned            g_cvcnt[BB * NCH];          // per-chunk valid count
__device__ unsigned long long  g_ckeys[BB * NCH * 256];    // chunk-local compacted keys
__device__ int                 g_nv[BB];
__device__ float4              g_boxes[BB][KK];
__device__ unsigned            g_paircnt[BB];              // 0 at entry, reset by K3 winner
__device__ unsigned            g_pairs[BB][PCAP];
__device__ unsigned            g_tiledone[BB];             // 0 at entry, reset by K3 winner

// ======== K1: warp-per-chunk compaction (8 anchors/lane, no barriers, no smem) ========
// key = (score_bits << 32) | (0xFFFFFFFF - idx): descending key order gives
// score desc, idx asc on ties (positive floats are bit-order-preserving).
__global__ void __launch_bounds__(256) k1_compact(const float* __restrict__ preds) {
    int b = blockIdx.y;
    int t = threadIdx.x, wid = t >> 5, lane = t & 31;

    int chunk = blockIdx.x * 8 + wid;            // one warp = one 256-anchor chunk
    if (chunk >= NCH) {
        cudaTriggerProgrammaticLaunchCompletion();
        return;
    }

    const float* sc = preds + (size_t)b * 5 * AA + (size_t)4 * AA;
    int a0 = chunk * 256 + lane * 8;             // 8 consecutive anchors per lane
    float4 sA = *(const float4*)(sc + a0);       // MLP=2: both loads independent
    float4 sB = *(const float4*)(sc + a0 + 4);

    unsigned m = (unsigned)(sA.x >= 0.1f)
               | ((unsigned)(sA.y >= 0.1f) << 1)
               | ((unsigned)(sA.z >= 0.1f) << 2)
               | ((unsigned)(sA.w >= 0.1f) << 3)
               | ((unsigned)(sB.x >= 0.1f) << 4)
               | ((unsigned)(sB.y >= 0.1f) << 5)
               | ((unsigned)(sB.z >= 0.1f) << 6)
               | ((unsigned)(sB.w >= 0.1f) << 7);
    int v = __popc(m);
    int inc = v;
    #pragma unroll
    for (int off = 1; off < 32; off <<= 1) {
        int n = __shfl_up_sync(0xFFFFFFFFu, inc, off);
        if (lane >= off) inc += n;
    }
    unsigned p = (unsigned)(inc - v);            // exclusive prefix within chunk

    unsigned long long* dst = &g_ckeys[((size_t)b * NCH + chunk) * 256];
    float ss[8] = {sA.x, sA.y, sA.z, sA.w, sB.x, sB.y, sB.z, sB.w};
    #pragma unroll
    for (int q = 0; q < 8; q++) {
        if ((m >> q) & 1u) {
            dst[p++] = ((unsigned long long)__float_as_uint(ss[q]) << 32) |
                       (unsigned long long)(0xFFFFFFFFu - (unsigned)(a0 + q));
        }
    }
    if (lane == 31) g_cvcnt[b * NCH + chunk] = (unsigned)inc;

    cudaTriggerProgrammaticLaunchCompletion();
}

// ======== K2: rank sort (thread-per-candidate, 4-way split scan) + tail fill ========
__global__ void __launch_bounds__(256) k2_rank_tail(const float* __restrict__ preds,
                                                    float* __restrict__ out) {
    // PDL: wait until K1's writes (g_cvcnt, g_ckeys) are visible
    cudaGridDependencySynchronize();

    int b = blockIdx.y, bl = blockIdx.x;       // bl in [0, RB)
    int t = threadIdx.x, wid = t >> 5, lane = t & 31;

    __shared__ unsigned long long sk[SCAP];    // 32 KB
    __shared__ unsigned scv[NCH];
    __shared__ unsigned scpre[NCH + 1];
    __shared__ unsigned short rp[64][4];
    __shared__ unsigned wsum[8];
    __shared__ unsigned s_cnt;

    if (t < NCH) scv[t] = g_cvcnt[b * NCH + t];
    __syncthreads();
    if (t == 0) {
        unsigned run = 0;
        for (int x = 0; x < NCH; x++) { scpre[x] = run; run += scv[x]; }
        scpre[NCH] = run;
        s_cnt = (run > SCAP) ? SCAP : run;
    }
    __syncthreads();
    unsigned cnt = s_cnt;
    int Nv = ((int)cnt < KK) ? (int)cnt : KK;
    if (bl == 0 && t == 0) g_nv[b] = Nv;

    // stage keys contiguously (warp per chunk)
    for (int cl = wid; cl < NCH; cl += 8) {
        unsigned base = scpre[cl], n = scv[cl];
        const unsigned long long* src = &g_ckeys[((size_t)b * NCH + cl) * 256];
        for (unsigned j = lane; j < n; j += 32) {
            unsigned d = base + j;
            if (d < SCAP) sk[d] = __ldg(&src[j]);
        }
    }
    __syncthreads();

    // rank scan: slot = candidate lane, seg = key segment
    int slot = t & 63, seg = t >> 6;           // seg is warp-uniform
    int npass = ((int)cnt + RB * 64 - 1) / (RB * 64);
    const float* basep = preds + (size_t)b * 5 * AA;

    for (int p = 0; p < npass; p++) {
        int c = p * (RB * 64) + bl * 64 + slot;
        bool act = (c < (int)cnt);
        unsigned long long mykey = act ? sk[c] : 0ULL;
        int s0 = (int)(((long long)cnt * seg) >> 2);
        int s1 = (int)(((long long)cnt * (seg + 1)) >> 2);
        int rpart = 0;
        if (act) {
            int mm = s0;
            for (; mm + 4 <= s1; mm += 4) {    // broadcast LDS: all lanes same address
                rpart += (sk[mm]     > mykey);
                rpart += (sk[mm + 1] > mykey);
                rpart += (sk[mm + 2] > mykey);
                rpart += (sk[mm + 3] > mykey);
            }
            for (; mm < s1; mm++) rpart += (sk[mm] > mykey);
        }
        rp[slot][seg] = (unsigned short)rpart;
        __syncthreads();
        if (seg == 0 && act) {
            int r = (int)rp[slot][0] + rp[slot][1] + rp[slot][2] + rp[slot][3];
            if (r < KK) {
                int idx = (int)(0xFFFFFFFFu - (unsigned)(mykey & 0xFFFFFFFFu));
                float score = __uint_as_float((unsigned)(mykey >> 32));
                float cx = __ldg(&basep[idx]);
                float cy = __ldg(&basep[AA + idx]);
                float ww = __ldg(&basep[2 * AA + idx]);
                float hh = __ldg(&basep[3 * AA + idx]);
                float hw = ww * 0.5f, hv = hh * 0.5f;
                float x1 = cx - hw, y1 = cy - hv, x2 = cx + hw, y2 = cy + hv;
                g_boxes[b][r] = make_float4(x1, y1, x2, y2);
                // scale = DET_SCALE/IMG_SIZE = [1.5, 1.0546875] (exact fp32)
                float s1f = x1 * 1.5f + 1.0f;
                float s2f = y1 * 1.0546875f + 1.0f;
                float s3f = x2 * 1.5f + 1.0f;
                float s4f = y2 * 1.0546875f + 1.0f;
                float* d = out + ((size_t)b * KK + r) * 5;
                d[0] = (s1f + s3f) * 0.5f;
                d[1] = (s2f + s4f) * 0.5f;
                d[2] = s3f - s1f;
                d[3] = s4f - s2f;
                d[4] = score;
                out[(size_t)BB * KK * 5 + (size_t)b * KK + r] = 1.0f;
            }
        }
        __syncthreads();
    }

    // tail fill: this block handles chunks bl, bl+RB, ...
    int needed = KK - Nv;
    if (needed > 0) {
        const float* sc = basep + (size_t)4 * AA;
        for (int cl = bl; cl < NCH; cl += RB) {
            int invpre = 256 * cl - (int)scpre[cl];   // block-uniform
            if (invpre < needed) {                    // uniform branch
                int a = cl * 256 + t;
                float s = __ldg(&sc[a]);
                bool inv = (s < 0.1f);
                unsigned bal = __ballot_sync(0xFFFFFFFFu, inv);
                if (lane == 0) wsum[wid] = (unsigned)__popc(bal);
                __syncthreads();
                int wbase = 0;
                #pragma unroll
                for (int q = 0; q < 8; q++) if (q < wid) wbase += (int)wsum[q];
                int r = invpre + wbase + __popc(bal & ((1u << lane) - 1u));
                if (inv && r < needed) {
                    int slotk = Nv + r;
                    float cx = basep[a], cy = basep[AA + a];
                    float ww = basep[2 * AA + a], hh = basep[3 * AA + a];
                    float hw = ww * 0.5f, hv = hh * 0.5f;
                    float x1 = cx - hw, y1 = cy - hv, x2 = cx + hw, y2 = cy + hv;
                    float s1f = x1 * 1.5f + 1.0f;
                    float s2f = y1 * 1.0546875f + 1.0f;
                    float s3f = x2 * 1.5f + 1.0f;
                    float s4f = y2 * 1.0546875f + 1.0f;
                    float* d = out + ((size_t)b * KK + slotk) * 5;
                    d[0] = (s1f + s3f) * 0.5f;
                    d[1] = (s2f + s4f) * 0.5f;
                    d[2] = s3f - s1f;
                    d[3] = s4f - s2f;
                    d[4] = -1.0f;
                    out[(size_t)BB * KK * 5 + (size_t)b * KK + slotk] = 0.0f;
                }
                __syncthreads();   // wsum reuse guard (uniform)
            }
        }
    }

    // PDL: allow K3's grid to launch as early as possible
    cudaTriggerProgrammaticLaunchCompletion();
}

// ======== K3: conflict pairs (64x64 tiles) + last-tile-done greedy resolution ========
__global__ void __launch_bounds__(256) k3_pairs_resolve(float* __restrict__ out) {
    // PDL: wait until K2's writes (g_nv, g_boxes, out) are visible
    cudaGridDependencySynchronize();

    int b = blockIdx.y, bx = blockIdx.x;
    int t = threadIdx.x;

    int Nv = __ldg(&g_nv[b]);
    int nt = (Nv + TILE - 1) / TILE;
    int T = nt * (nt + 1) / 2;
    if (bx >= T) return;

    __shared__ float4 sbi[TILE];
    __shared__ float  sai[TILE];
    __shared__ float4 sbj[TILE];
    __shared__ float  saj[TILE];
    __shared__ int    swin;
    __shared__ unsigned sp[PCAP];        // 2 KB
    __shared__ unsigned char skeep[KK];  // 2 KB

    int i = 0, S = 0;
    while (bx >= S + (nt - i)) { S += nt - i; i++; }
    int j = i + (bx - S);
    int i0 = i * TILE, j0 = j * TILE;

    if (t < TILE) {
        float4 bi = (i0 + t < Nv) ? g_boxes[b][i0 + t] : make_float4(0.f, 0.f, 0.f, 0.f);
        sbi[t] = bi; sai[t] = (bi.z - bi.x) * (bi.w - bi.y);
    } else if (t < 2 * TILE) {
        int u = t - TILE;
        float4 bj = (j0 + u < Nv) ? g_boxes[b][j0 + u] : make_float4(0.f, 0.f, 0.f, 0.f);
        sbj[u] = bj; saj[u] = (bj.z - bj.x) * (bj.w - bj.y);
    }
    __syncthreads();

    int jl = t & 63;
    int jj = j0 + jl;
    if (jj < Nv) {
        float4 bj = sbj[jl];
        float aj = saj[jl];
        #pragma unroll
        for (int q = 0; q < 16; q++) {
            int ii = (t >> 6) + q * 4;
            int gi = i0 + ii;
            if (gi >= Nv || gi >= jj) continue;
            float4 bi = sbi[ii];
            float lx = fmaxf(bi.x, bj.x), ly = fmaxf(bi.y, bj.y);
            float rx = fminf(bi.z, bj.z), ry = fminf(bi.w, bj.w);
            float iw = fmaxf(rx - lx, 0.f), ih = fmaxf(ry - ly, 0.f);
            float inter = iw * ih;
            // iou > 0.7  <=>  inter > 0.7 * union   (union > 0)
            if (inter > 0.7f * (sai[ii] + aj - inter)) {
                unsigned pos = atomicAdd(&g_paircnt[b], 1u);
                if (pos < PCAP)
                    g_pairs[b][pos] = ((unsigned)jj << 16) | (unsigned)gi;
            }
        }
    }
    __syncthreads();

    if (t == 0) {
        __threadfence();                                  // publish this tile's pair writes
        unsigned old = atomicAdd(&g_tiledone[b], 1u);
        swin = (old == (unsigned)(T - 1)) ? 1 : 0;
    }
    __syncthreads();
    if (!swin) return;

    // ---- winner block: exact greedy resolution ----
    __threadfence();
    unsigned n = g_paircnt[b];
    if (n > PCAP) n = PCAP;

    for (int k = t; k < KK; k += 256) skeep[k] = (k < Nv) ? 1 : 0;
    for (unsigned p = t; p < n; p += 256) sp[p] = g_pairs[b][p];
    __syncthreads();

    if (t == 0) {
        // sort ascending by packed (j<<16 | i): process suppression targets j ascending
        for (unsigned x = 1; x < n; x++) {
            unsigned v = sp[x];
            int y = (int)x - 1;
            while (y >= 0 && sp[y] > v) { sp[y + 1] = sp[y]; y--; }
            sp[y + 1] = v;
        }
        for (unsigned x = 0; x < n; x++) {
            unsigned v = sp[x];
            int jd = (int)(v >> 16), is = (int)(v & 0xFFFFu);
            if (skeep[is] && skeep[jd]) {
                skeep[jd] = 0;
                out[(size_t)BB * KK * 5 + (size_t)b * KK + jd] = 0.0f;
            }
        }
        g_paircnt[b]  = 0u;   // restore zero-state for next launch
        g_tiledone[b] = 0u;
    }
}

// ---------------- launch (serial PDL pipeline, round-8 structure) ----------------
static void launch_pdl2(void (*kern)(const float*, float*),
                        dim3 grid, const float* preds, float* out) {
    cudaLaunchConfig_t cfg = {};
    cfg.gridDim = grid; cfg.blockDim = dim3(256, 1, 1);
    cfg.dynamicSmemBytes = 0; cfg.stream = 0;
    cudaLaunchAttribute attr[1];
    attr[0].id = cudaLaunchAttributeProgrammaticStreamSerialization;
    attr[0].val.programmaticStreamSerializationAllowed = 1;
    cfg.attrs = attr; cfg.numAttrs = 1;
    cudaLaunchKernelEx(&cfg, kern, preds, out);
}
static void launch_pdl1(void (*kern)(float*), dim3 grid, float* out) {
    cudaLaunchConfig_t cfg = {};
    cfg.gridDim = grid; cfg.blockDim = dim3(256, 1, 1);
    cfg.dynamicSmemBytes = 0; cfg.stream = 0;
    cudaLaunchAttribute attr[1];
    attr[0].id = cudaLaunchAttributeProgrammaticStreamSerialization;
    attr[0].val.programmaticStreamSerializationAllowed = 1;
    cfg.attrs = attr; cfg.numAttrs = 1;
    cudaLaunchKernelEx(&cfg, kern, out);
}

extern "C" void kernel_launch(void* const* d_in, const int* in_sizes, int n_in,
                              void* d_out, int out_size) {
    const float* preds = (const float*)d_in[0];
    float* out = (float*)d_out;
    (void)in_sizes; (void)n_in; (void)out_size;

    k1_compact<<<dim3(14, BB), 256>>>(preds);             // 14*8 warps >= 105 chunks
    launch_pdl2(k2_rank_tail, dim3(RB, BB), preds, out);  // PDL on K1
    launch_pdl1(k3_pairs_resolve, dim3(K3B, BB), out);    // PDL on K2
}